// round 1
// baseline (speedup 1.0000x reference)
#include <cuda_runtime.h>

#define N_USERS 50000
#define N_ENT   150000
#define NN      200000
#define NE      2000000
#define NB      8192
#define TOT     176   // 64 + 64 + 32 + 16

// Scratch (allocation-free rule: __device__ globals)
__device__ float g_ego [NN * 64];
__device__ float g_ego2[NN * 64];
__device__ float g_side[NN * 64];
__device__ float g_all [NN * TOT];

// ---------------------------------------------------------------------------
// ego = concat(user_embed, entity_embed); also embs[0] slice of all_emb
// one thread per float4 of the 64-wide row
__global__ void k_init(const float* __restrict__ ue, const float* __restrict__ ee) {
    int i = blockIdx.x * blockDim.x + threadIdx.x;   // over NN*16
    if (i >= NN * 16) return;
    int n = i >> 4, c = i & 15;
    float4 v = (n < N_USERS)
        ? ((const float4*)ue)[(size_t)n * 16 + c]
        : ((const float4*)ee)[(size_t)(n - N_USERS) * 16 + c];
    ((float4*)g_ego)[i] = v;
    // all_emb row stride 176 floats = 704B (16B aligned), cols [0,64)
    ((float4*)(g_all + (size_t)n * TOT))[c] = v;
}

__global__ void k_zero(float4* __restrict__ p, int n4) {
    int i = blockIdx.x * blockDim.x + threadIdx.x;
    if (i < n4) p[i] = make_float4(0.f, 0.f, 0.f, 0.f);
}

// ---------------------------------------------------------------------------
// side[rows[e]] += vals[e] * src[cols[e]]   (thread = one float4 chunk of one edge)
template<int DIN>
__global__ void k_scatter(const int* __restrict__ rows, const int* __restrict__ cols,
                          const float* __restrict__ vals, const float* __restrict__ src) {
    constexpr int C = DIN / 4;
    int t = blockIdx.x * blockDim.x + threadIdx.x;
    if (t >= NE * C) return;
    int e = t / C, c = t % C;
    int r  = rows[e];
    int cl = cols[e];
    float v = vals[e];
    float4 x = ((const float4*)src)[(size_t)cl * C + c];
    float* d = g_side + (size_t)r * DIN + c * 4;
    atomicAdd(d + 0, v * x.x);
    atomicAdd(d + 1, v * x.y);
    atomicAdd(d + 2, v * x.z);
    atomicAdd(d + 3, v * x.w);
}

// ---------------------------------------------------------------------------
// new_ego = leaky((ego+side)@Wg + bg) + leaky((ego*side)@Wb + bb)
// all_emb[:, OFF:OFF+DOUT] = l2norm(new_ego)
// One warp per node; weights staged in smem.
template<int DIN, int DOUT, int OFF>
__global__ void k_transform(const float* __restrict__ Wg, const float* __restrict__ bg,
                            const float* __restrict__ Wb, const float* __restrict__ bb,
                            const float* __restrict__ src, float* __restrict__ dst) {
    __shared__ float sWg[DIN * DOUT];
    __shared__ float sWb[DIN * DOUT];
    __shared__ float sbg[DOUT];
    __shared__ float sbb[DOUT];
    __shared__ float s1[8][DIN];
    __shared__ float s2[8][DIN];

    int tid = threadIdx.x;
    for (int i = tid; i < DIN * DOUT; i += blockDim.x) { sWg[i] = Wg[i]; sWb[i] = Wb[i]; }
    for (int i = tid; i < DOUT; i += blockDim.x)       { sbg[i] = bg[i]; sbb[i] = bb[i]; }
    __syncthreads();

    int w = tid >> 5, lane = tid & 31;
    int gw = blockIdx.x * 8 + w;
    int nw = gridDim.x * 8;
    constexpr int CO = (DOUT + 31) / 32;

    for (int n = gw; n < NN; n += nw) {
        #pragma unroll
        for (int c = 0; c < DIN / 32; c++) {
            int k = lane + 32 * c;
            float e = src[(size_t)n * DIN + k];
            float s = g_side[(size_t)n * DIN + k];
            s1[w][k] = e + s;
            s2[w][k] = e * s;
        }
        __syncwarp();

        float a1[CO], a2[CO];
        #pragma unroll
        for (int c = 0; c < CO; c++) { a1[c] = 0.f; a2[c] = 0.f; }

        #pragma unroll 8
        for (int k = 0; k < DIN; k++) {
            float x1 = s1[w][k];
            float x2 = s2[w][k];
            #pragma unroll
            for (int c = 0; c < CO; c++) {
                int j = lane + 32 * c;
                if (j < DOUT) {
                    a1[c] = fmaf(x1, sWg[k * DOUT + j], a1[c]);
                    a2[c] = fmaf(x2, sWb[k * DOUT + j], a2[c]);
                }
            }
        }

        float out[CO];
        float ss = 0.f;
        #pragma unroll
        for (int c = 0; c < CO; c++) {
            int j = lane + 32 * c;
            if (j < DOUT) {
                float v1 = a1[c] + sbg[j]; v1 = v1 > 0.f ? v1 : 0.01f * v1;
                float v2 = a2[c] + sbb[j]; v2 = v2 > 0.f ? v2 : 0.01f * v2;
                float o = v1 + v2;
                out[c] = o;
                dst[(size_t)n * DOUT + j] = o;
                ss += o * o;
            }
        }
        #pragma unroll
        for (int o = 16; o > 0; o >>= 1) ss += __shfl_xor_sync(0xffffffffu, ss, o);
        float inv = 1.0f / fmaxf(sqrtf(ss), 1e-12f);
        #pragma unroll
        for (int c = 0; c < CO; c++) {
            int j = lane + 32 * c;
            if (j < DOUT) g_all[(size_t)n * TOT + OFF + j] = out[c] * inv;
        }
        __syncwarp();
    }
}

// ---------------------------------------------------------------------------
// Warp per sample: pos/neg dot products over 176 dims.
__global__ void k_score(const int* __restrict__ users, const int* __restrict__ pos,
                        const int* __restrict__ neg, float* __restrict__ out) {
    int wid  = (blockIdx.x * blockDim.x + threadIdx.x) >> 5;
    int lane = threadIdx.x & 31;
    if (wid >= NB) return;
    const float* u = g_all + (size_t)users[wid] * TOT;
    const float* p = g_all + (size_t)(N_USERS + pos[wid]) * TOT;
    const float* q = g_all + (size_t)(N_USERS + neg[wid]) * TOT;
    float sp = 0.f, sn = 0.f;
    #pragma unroll
    for (int k = lane; k < TOT; k += 32) {
        float uv = u[k];
        sp += uv * p[k];
        sn += uv * q[k];
    }
    #pragma unroll
    for (int o = 16; o > 0; o >>= 1) {
        sp += __shfl_xor_sync(0xffffffffu, sp, o);
        sn += __shfl_xor_sync(0xffffffffu, sn, o);
    }
    if (lane == 0) { out[2 * wid] = sp; out[2 * wid + 1] = sn; }
}

// ---------------------------------------------------------------------------
extern "C" void kernel_launch(void* const* d_in, const int* in_sizes, int n_in,
                              void* d_out, int out_size) {
    const int*   users = (const int*)  d_in[0];
    const int*   pos   = (const int*)  d_in[1];
    const int*   neg   = (const int*)  d_in[2];
    const int*   rows  = (const int*)  d_in[3];
    const int*   cols  = (const int*)  d_in[4];
    const float* vals  = (const float*)d_in[5];
    const float* ue    = (const float*)d_in[6];
    const float* ee    = (const float*)d_in[7];
    const float* W[3][4];
    for (int l = 0; l < 3; l++)
        for (int j = 0; j < 4; j++)
            W[l][j] = (const float*)d_in[8 + 4 * l + j];

    float *p_ego, *p_ego2, *p_side;
    cudaGetSymbolAddress((void**)&p_ego,  g_ego);
    cudaGetSymbolAddress((void**)&p_ego2, g_ego2);
    cudaGetSymbolAddress((void**)&p_side, g_side);

    const int TB = 256;

    k_init<<<(NN * 16 + TB - 1) / TB, TB>>>(ue, ee);

    // Layer 0: din=64 -> dout=64, src=g_ego, dst=g_ego2, all_emb offset 64
    k_zero<<<(NN * 16 + TB - 1) / TB, TB>>>((float4*)p_side, NN * 16);
    k_scatter<64><<<(NE * 16 + TB - 1) / TB, TB>>>(rows, cols, vals, p_ego);
    k_transform<64, 64, 64><<<592, TB>>>(W[0][0], W[0][1], W[0][2], W[0][3], p_ego, p_ego2);

    // Layer 1: din=64 -> dout=32, src=g_ego2, dst=g_ego, offset 128
    k_zero<<<(NN * 16 + TB - 1) / TB, TB>>>((float4*)p_side, NN * 16);
    k_scatter<64><<<(NE * 16 + TB - 1) / TB, TB>>>(rows, cols, vals, p_ego2);
    k_transform<64, 32, 128><<<592, TB>>>(W[1][0], W[1][1], W[1][2], W[1][3], p_ego2, p_ego);

    // Layer 2: din=32 -> dout=16, src=g_ego, dst=g_ego2, offset 160
    k_zero<<<(NN * 8 + TB - 1) / TB, TB>>>((float4*)p_side, NN * 8);
    k_scatter<32><<<(NE * 8 + TB - 1) / TB, TB>>>(rows, cols, vals, p_ego);
    k_transform<32, 16, 160><<<592, TB>>>(W[2][0], W[2][1], W[2][2], W[2][3], p_ego, p_ego2);

    k_score<<<(NB * 32 + TB - 1) / TB, TB>>>(users, pos, neg, (float*)d_out);
}

// round 3
// speedup vs baseline: 1.6231x; 1.6231x over previous
#include <cuda_runtime.h>

#define N_USERS 50000
#define N_ENT   150000
#define NN      200000
#define NE      2000000
#define NB      8192
#define TOT     176   // 64 + 64 + 32 + 16
#define NCHUNK  256
#define CHSZ    782   // ceil(NN/256)

// Scratch (allocation-free rule: __device__ globals)
__device__ float g_ego [NN * 64];
__device__ float g_ego2[NN * 64];
__device__ float g_all [NN * TOT];
__device__ int   g_deg   [NN];
__device__ int   g_off   [NN];
__device__ int   g_rowptr[NN];
__device__ int   g_csum  [NCHUNK];
__device__ int   g_coff  [NCHUNK];
__device__ int2  g_edge  [NE];      // (col, bitcast(val)) sorted by row

// ---------------------------------------------------------------------------
__global__ void k_init(const float* __restrict__ ue, const float* __restrict__ ee) {
    int i = blockIdx.x * blockDim.x + threadIdx.x;   // over NN*16
    if (i >= NN * 16) return;
    int n = i >> 4, c = i & 15;
    float4 v = (n < N_USERS)
        ? ((const float4*)ue)[(size_t)n * 16 + c]
        : ((const float4*)ee)[(size_t)(n - N_USERS) * 16 + c];
    ((float4*)g_ego)[i] = v;
    ((float4*)(g_all + (size_t)n * TOT))[c] = v;
}

__global__ void k_zero2(int* __restrict__ a, int* __restrict__ b, int n) {
    int i = blockIdx.x * blockDim.x + threadIdx.x;
    if (i < n) { a[i] = 0; b[i] = 0; }
}

// ---------------------------------------------------------------------------
// CSR build
__global__ void k_hist(const int* __restrict__ rows) {
    int e = blockIdx.x * blockDim.x + threadIdx.x;
    if (e < NE) atomicAdd(&g_deg[rows[e]], 1);
}

__global__ void k_csum() {  // 256 blocks x 256 threads: chunk sums
    __shared__ int s[256];
    int b = blockIdx.x, tid = threadIdx.x;
    int beg = b * CHSZ, end = min(beg + CHSZ, NN);
    int acc = 0;
    for (int i = beg + tid; i < end; i += 256) acc += g_deg[i];
    s[tid] = acc; __syncthreads();
    for (int o = 128; o > 0; o >>= 1) { if (tid < o) s[tid] += s[tid + o]; __syncthreads(); }
    if (tid == 0) g_csum[b] = s[0];
}

__global__ void k_scan256() {  // 1 block: exclusive scan of chunk sums
    __shared__ int s[256];
    int tid = threadIdx.x;
    int v = g_csum[tid];
    s[tid] = v; __syncthreads();
    for (int o = 1; o < 256; o <<= 1) {
        int t = (tid >= o) ? s[tid - o] : 0;
        __syncthreads(); s[tid] += t; __syncthreads();
    }
    g_coff[tid] = s[tid] - v;
}

__global__ void k_rowptr() {  // 256 blocks: scan within chunk
    __shared__ int s[256];
    __shared__ int stot;
    int b = blockIdx.x, tid = threadIdx.x;
    int beg = b * CHSZ, end = min(beg + CHSZ, NN);
    int running = g_coff[b];
    for (int t = beg; t < end; t += 256) {
        int idx = t + tid;
        int v = (idx < end) ? g_deg[idx] : 0;
        s[tid] = v; __syncthreads();
        for (int o = 1; o < 256; o <<= 1) {
            int u = (tid >= o) ? s[tid - o] : 0;
            __syncthreads(); s[tid] += u; __syncthreads();
        }
        if (idx < end) g_rowptr[idx] = running + s[tid] - v;
        if (tid == 255) stot = s[255];
        __syncthreads();
        running += stot;
        __syncthreads();
    }
}

__global__ void k_place(const int* __restrict__ rows, const int* __restrict__ cols,
                        const float* __restrict__ vals) {
    int e = blockIdx.x * blockDim.x + threadIdx.x;
    if (e >= NE) return;
    int r = rows[e];
    int p = g_rowptr[r] + atomicAdd(&g_off[r], 1);
    g_edge[p] = make_int2(cols[e], __float_as_int(vals[e]));
}

// ---------------------------------------------------------------------------
// Fused: side-gather + GC/BI transform + l2norm. One warp per node.
// Half-warp (lanes 0-15) handles GC matrix, lanes 16-31 handle BI.
// Each active lane owns 4 adjacent output columns (float4 weight loads).
template<int DIN, int DOUT, int OFF>
__global__ void k_layer(const float* __restrict__ Wg, const float* __restrict__ bg,
                        const float* __restrict__ Wb, const float* __restrict__ bb,
                        const float* __restrict__ src, float* __restrict__ dst) {
    constexpr int KC  = DIN / 32;
    constexpr int LPM = DOUT / 4;   // lanes per matrix
    constexpr int WPB = 8;
    __shared__ float sW[2 * DIN * DOUT];
    __shared__ float sB[2 * DOUT];
    __shared__ float sx[WPB][2][DIN];

    int tid = threadIdx.x;
    for (int i = tid; i < DIN * DOUT; i += blockDim.x) { sW[i] = Wg[i]; sW[DIN * DOUT + i] = Wb[i]; }
    for (int i = tid; i < DOUT; i += blockDim.x)       { sB[i] = bg[i]; sB[DOUT + i] = bb[i]; }
    __syncthreads();

    int w = tid >> 5, lane = tid & 31;
    int h  = lane >> 4;          // 0 = GC, 1 = BI
    int jl = lane & 15;
    bool act = jl < LPM;
    int jc = act ? jl : 0;
    const float* wbase = sW + h * DIN * DOUT;
    const float* xbase = &sx[w][h][0];

    for (int n = blockIdx.x * WPB + w; n < NN; n += gridDim.x * WPB) {
        float er[KC], acc[KC];
        #pragma unroll
        for (int c = 0; c < KC; c++) {
            er[c]  = src[(size_t)n * DIN + lane + 32 * c];
            acc[c] = 0.f;
        }
        int s0 = g_rowptr[n], cnt = g_deg[n];
        for (int base = 0; base < cnt; base += 32) {
            int2 ev = make_int2(0, 0);
            if (base + lane < cnt) ev = g_edge[s0 + base + lane];
            int vn = min(32, cnt - base);
            for (int m = 0; m < vn; m++) {
                int   col = __shfl_sync(0xffffffffu, ev.x, m);
                float val = __int_as_float(__shfl_sync(0xffffffffu, ev.y, m));
                #pragma unroll
                for (int c = 0; c < KC; c++)
                    acc[c] = fmaf(val, src[(size_t)col * DIN + lane + 32 * c], acc[c]);
            }
        }
        #pragma unroll
        for (int c = 0; c < KC; c++) {
            int k = lane + 32 * c;
            sx[w][0][k] = er[c] + acc[c];
            sx[w][1][k] = er[c] * acc[c];
        }
        __syncwarp();

        float4 a = make_float4(0.f, 0.f, 0.f, 0.f);
        #pragma unroll
        for (int k4 = 0; k4 < DIN; k4 += 4) {
            float4 xv = *(const float4*)(xbase + k4);
            #pragma unroll
            for (int i = 0; i < 4; i++) {
                float4 wv = ((const float4*)(wbase + (k4 + i) * DOUT))[jc];
                float xk = (&xv.x)[i];
                a.x = fmaf(xk, wv.x, a.x);
                a.y = fmaf(xk, wv.y, a.y);
                a.z = fmaf(xk, wv.z, a.z);
                a.w = fmaf(xk, wv.w, a.w);
            }
        }
        float4 bv = ((const float4*)(sB + h * DOUT))[jc];
        float4 v;
        v.x = a.x + bv.x; v.x = v.x > 0.f ? v.x : 0.01f * v.x;
        v.y = a.y + bv.y; v.y = v.y > 0.f ? v.y : 0.01f * v.y;
        v.z = a.z + bv.z; v.z = v.z > 0.f ? v.z : 0.01f * v.z;
        v.w = a.w + bv.w; v.w = v.w > 0.f ? v.w : 0.01f * v.w;
        // combine GC + BI halves
        float4 o;
        o.x = v.x + __shfl_xor_sync(0xffffffffu, v.x, 16);
        o.y = v.y + __shfl_xor_sync(0xffffffffu, v.y, 16);
        o.z = v.z + __shfl_xor_sync(0xffffffffu, v.z, 16);
        o.w = v.w + __shfl_xor_sync(0xffffffffu, v.w, 16);
        float ss = o.x * o.x + o.y * o.y + o.z * o.z + o.w * o.w;
        #pragma unroll
        for (int off = LPM / 2; off > 0; off >>= 1)
            ss += __shfl_xor_sync(0xffffffffu, ss, off);
        float inv = 1.0f / fmaxf(sqrtf(ss), 1e-12f);
        if (h == 0 && act) {
            ((float4*)(dst + (size_t)n * DOUT))[jl] = o;
            float4 on = make_float4(o.x * inv, o.y * inv, o.z * inv, o.w * inv);
            ((float4*)(g_all + (size_t)n * TOT + OFF))[jl] = on;
        }
        __syncwarp();
    }
}

// ---------------------------------------------------------------------------
__global__ void k_score(const int* __restrict__ users, const int* __restrict__ pos,
                        const int* __restrict__ neg, float* __restrict__ out) {
    int wid  = (blockIdx.x * blockDim.x + threadIdx.x) >> 5;
    int lane = threadIdx.x & 31;
    if (wid >= NB) return;
    const float* u = g_all + (size_t)users[wid] * TOT;
    const float* p = g_all + (size_t)(N_USERS + pos[wid]) * TOT;
    const float* q = g_all + (size_t)(N_USERS + neg[wid]) * TOT;
    float sp = 0.f, sn = 0.f;
    #pragma unroll
    for (int k = lane; k < TOT; k += 32) {
        float uv = u[k];
        sp += uv * p[k];
        sn += uv * q[k];
    }
    #pragma unroll
    for (int o = 16; o > 0; o >>= 1) {
        sp += __shfl_xor_sync(0xffffffffu, sp, o);
        sn += __shfl_xor_sync(0xffffffffu, sn, o);
    }
    if (lane == 0) { out[2 * wid] = sp; out[2 * wid + 1] = sn; }
}

// ---------------------------------------------------------------------------
extern "C" void kernel_launch(void* const* d_in, const int* in_sizes, int n_in,
                              void* d_out, int out_size) {
    const int*   users = (const int*)  d_in[0];
    const int*   pos   = (const int*)  d_in[1];
    const int*   neg   = (const int*)  d_in[2];
    const int*   rows  = (const int*)  d_in[3];
    const int*   cols  = (const int*)  d_in[4];
    const float* vals  = (const float*)d_in[5];
    const float* ue    = (const float*)d_in[6];
    const float* ee    = (const float*)d_in[7];
    const float* W[3][4];
    for (int l = 0; l < 3; l++)
        for (int j = 0; j < 4; j++)
            W[l][j] = (const float*)d_in[8 + 4 * l + j];

    float *p_ego, *p_ego2;
    int *p_deg, *p_off;
    cudaGetSymbolAddress((void**)&p_ego,  g_ego);
    cudaGetSymbolAddress((void**)&p_ego2, g_ego2);
    cudaGetSymbolAddress((void**)&p_deg,  g_deg);
    cudaGetSymbolAddress((void**)&p_off,  g_off);

    const int TB = 256;

    k_init<<<(NN * 16 + TB - 1) / TB, TB>>>(ue, ee);

    // CSR build
    k_zero2<<<(NN + TB - 1) / TB, TB>>>(p_deg, p_off, NN);
    k_hist<<<(NE + TB - 1) / TB, TB>>>(rows);
    k_csum<<<NCHUNK, 256>>>();
    k_scan256<<<1, 256>>>();
    k_rowptr<<<NCHUNK, 256>>>();
    k_place<<<(NE + TB - 1) / TB, TB>>>(rows, cols, vals);

    // Layers (fused gather + transform + l2norm)
    k_layer<64, 64,  64><<<592, TB>>>(W[0][0], W[0][1], W[0][2], W[0][3], p_ego,  p_ego2);
    k_layer<64, 32, 128><<<592, TB>>>(W[1][0], W[1][1], W[1][2], W[1][3], p_ego2, p_ego);
    k_layer<32, 16, 160><<<592, TB>>>(W[2][0], W[2][1], W[2][2], W[2][3], p_ego,  p_ego2);

    k_score<<<(NB * 32 + TB - 1) / TB, TB>>>(users, pos, neg, (float*)d_out);
}